// round 2
// baseline (speedup 1.0000x reference)
#include <cuda_runtime.h>
#include <stdint.h>

// Problem: emb_in [2048, 32] f32, sum_weights [2048] f32.
// Output [2048*2048, 65] f32:
//   row k = i*2048 + j:
//     out[k][0:32]  = emb_in[i]
//     out[k][32:64] = emb_in[j]
//     out[k][64]    = sum_weights[j]
//
// 1.09 GB of output, ~256 KB of input -> pure store-bandwidth bound.
// Strategy: flatten output to float4 stream (aligned STG.128), recover
// (row, col) per element with a single udiv-by-65 (umulhi reciprocal).

#define N_ROWS   2048
#define FDIM     32
#define ROW_LEN  65                       // 2*FDIM + 1
#define TOTAL_F  (2048u * 2048u * 65u)    // 272,629,760 floats
#define TOTAL_F4 (TOTAL_F / 4u)           // 68,157,440 float4 (exact)

__global__ __launch_bounds__(256, 8)
void no_sparsity_kernel(const float* __restrict__ emb,
                        const float* __restrict__ w,
                        float4* __restrict__ out)
{
    unsigned g4 = blockIdx.x * blockDim.x + threadIdx.x;
    if (g4 >= TOTAL_F4) return;

    unsigned g = g4 * 4u;

    float v[4];
#pragma unroll
    for (int e = 0; e < 4; ++e) {
        unsigned idx = g + (unsigned)e;          // flat float index, < 2^32
        unsigned k   = idx / 65u;                // output row (umulhi-based)
        unsigned c   = idx - k * 65u;            // column within row, 0..64
        unsigned i   = k >> 11;                  // k / 2048
        unsigned j   = k & 2047u;                // k % 2048

        float val;
        if (c < 32u) {
            val = __ldg(emb + i * 32u + c);
        } else if (c < 64u) {
            val = __ldg(emb + j * 32u + (c - 32u));
        } else {
            val = __ldg(w + j);
        }
        v[e] = val;
    }

    out[g4] = make_float4(v[0], v[1], v[2], v[3]);
}

extern "C" void kernel_launch(void* const* d_in, const int* in_sizes, int n_in,
                              void* d_out, int out_size)
{
    const float* emb = (const float*)d_in[0];   // [2048, 32] f32
    const float* w   = (const float*)d_in[1];   // [2048]     f32
    float4* out      = (float4*)d_out;          // [2048*2048, 65] f32 (flattened)

    const unsigned threads = 256;
    const unsigned blocks  = (TOTAL_F4 + threads - 1) / threads;  // 266,240 exact

    no_sparsity_kernel<<<blocks, threads>>>(emb, w, out);
}

// round 4
// speedup vs baseline: 1.4464x; 1.4464x over previous
#include <cuda_runtime.h>
#include <stdint.h>

// Problem: emb_in [2048, 32] f32, sum_weights [2048] f32.
// Output [2048*2048, 65] f32, row k = i*2048 + j:
//   out[k][0:32]=emb[i], out[k][32:64]=emb[j], out[k][64]=w[j].
//
// R2 lesson: per-element udiv+gather made the kernel issue/ALU-bound
// (issue 77%, alu 45%, DRAM only 46%). R3: stage a 64-row chunk in smem
// with structured fills, then stream it out as aligned float4 copies.
//
// Alignment: chunk start k0 is a multiple of 64; 65 == 1 (mod 4), so
// k0*65 is a multiple of 4 -> the 64*65-float chunk is an exact,
// 16B-aligned float4 region. 64 | 2048, so a chunk never crosses i.

#define N_ROWS    2048
#define ROW_LEN   65
#define R_CHUNK   64
#define CHUNK_F   (R_CHUNK * ROW_LEN)        // 4160 floats
#define CHUNK_F4  (CHUNK_F / 4)              // 1040 float4
#define N_CHUNKS  (N_ROWS * N_ROWS / R_CHUNK)  // 65536 blocks

__global__ __launch_bounds__(256)
void no_sparsity_stage_kernel(const float* __restrict__ emb,
                              const float* __restrict__ w,
                              float4* __restrict__ out4)
{
    __shared__ __align__(16) float s[CHUNK_F];   // 16,640 B

    const unsigned k0 = blockIdx.x * (unsigned)R_CHUNK;  // first output row
    const unsigned i  = k0 >> 11;                        // constant per block
    const unsigned j0 = k0 & 2047u;

    const int tid  = threadIdx.x;
    const int lane = tid & 31;
    const int wr   = tid >> 5;                           // warp id, 0..7

    // Each lane holds emb[i][lane]; one broadcast 128B line, L1-resident.
    const float a = __ldg(emb + i * 32u + lane);

    // ---- Phase 1: fill smem image. Warp wr handles rows wr, wr+8, ... ----
#pragma unroll
    for (int r = wr; r < R_CHUNK; r += 8) {
        const unsigned j = j0 + (unsigned)r;
        const float b = __ldg(emb + j * 32u + lane);     // coalesced 128B row
        float* srow = s + r * ROW_LEN;
        srow[lane]      = a;                             // cols 0..31
        srow[32 + lane] = b;                             // cols 32..63
        if (lane == 0) srow[64] = __ldg(w + j);          // col 64
    }
    __syncthreads();

    // ---- Phase 2: stream chunk to gmem as aligned float4 copies ----
    const float4* s4    = (const float4*)s;
    const unsigned base = (k0 * (unsigned)ROW_LEN) >> 2; // exact (k0 % 4 == 0)

#pragma unroll
    for (int t = tid; t < CHUNK_F4; t += 256) {
        out4[base + t] = s4[t];
    }
}

extern "C" void kernel_launch(void* const* d_in, const int* in_sizes, int n_in,
                              void* d_out, int out_size)
{
    const float* emb = (const float*)d_in[0];   // [2048, 32] f32
    const float* w   = (const float*)d_in[1];   // [2048]     f32
    float4* out4     = (float4*)d_out;

    no_sparsity_stage_kernel<<<N_CHUNKS, 256>>>(emb, w, out4);
}

// round 9
// speedup vs baseline: 1.9186x; 1.3265x over previous
#include <cuda_runtime.h>
#include <stdint.h>

// Problem: emb_in [2048, 32] f32, sum_weights [2048] f32.
// Output [2048*2048, 65] f32, row k = i*2048 + j:
//   out[k][0:32]=emb[i], out[k][32:64]=emb[j], out[k][64]=w[j].
//
// R4 lesson: smem stage + LDS/STG copy-out is L1tex-bound (L1 71.7%,
// DRAM only 65.8%, issue 18%). R8 (retry of R5 after infra failure):
// keep the structured smem fill, drain each chunk with ONE
// cp.async.bulk (TMA) store per block. The TMA engine reads smem
// directly and writes gmem via the async proxy — no LDS, no STG,
// no register round-trip, no L1tex store wavefronts.
//
// Chunk = 128 consecutive output rows: 128*65*4 = 33,280 B, contiguous
// in gmem (base = blockIdx*33280, 16B-aligned), so a 1D bulk copy works
// with no tensormap. 128 | 2048 -> a chunk never crosses i.

#define N_ROWS     2048
#define ROW_LEN    65
#define R_CHUNK    128
#define CHUNK_F    (R_CHUNK * ROW_LEN)          // 8320 floats
#define CHUNK_B    (CHUNK_F * 4)                // 33,280 bytes (mult of 16)
#define N_CHUNKS   (N_ROWS * N_ROWS / R_CHUNK)  // 32768 blocks

__global__ __launch_bounds__(256)
void no_sparsity_tma_kernel(const float* __restrict__ emb,
                            const float* __restrict__ w,
                            float* __restrict__ out)
{
    __shared__ __align__(16) float s[CHUNK_F];

    const unsigned k0 = blockIdx.x * (unsigned)R_CHUNK;  // first output row
    const unsigned i  = k0 >> 11;                        // constant per block
    const unsigned j0 = k0 & 2047u;

    const int tid  = threadIdx.x;
    const int lane = tid & 31;
    const int wr   = tid >> 5;                           // warp id, 0..7

    // emb[i][lane]: one broadcast 128B line, L1-resident across the block.
    const float a = __ldg(emb + i * 32u + lane);

    // ---- Fill smem image. Warp wr handles rows wr, wr+8, ... (16 rows) ----
    // Bank check: row stride 65 == 1 (mod 32) -> bank = (r + lane) % 32,
    // distinct per lane, conflict-free.
#pragma unroll
    for (int r = wr; r < R_CHUNK; r += 8) {
        const unsigned j = j0 + (unsigned)r;
        const float b = __ldg(emb + j * 32u + lane);     // coalesced 128B row
        float* srow = s + r * ROW_LEN;
        srow[lane]      = a;                             // cols 0..31
        srow[32 + lane] = b;                             // cols 32..63
        if (lane == 0) srow[64] = __ldg(w + j);          // col 64
    }
    __syncthreads();

    // Order generic-proxy STS writes before the async-proxy TMA read.
    asm volatile("fence.proxy.async.shared::cta;" ::: "memory");

    // ---- Drain: one bulk TMA store, smem -> gmem ----
    if (tid == 0) {
        const float* dst = out + (size_t)blockIdx.x * (size_t)CHUNK_F;
        uint32_t saddr = (uint32_t)__cvta_generic_to_shared(s);
        asm volatile(
            "cp.async.bulk.global.shared::cta.bulk_group [%0], [%1], %2;"
            :: "l"(dst), "r"(saddr), "r"((unsigned)CHUNK_B)
            : "memory");
        asm volatile("cp.async.bulk.commit_group;" ::: "memory");
        // Full wait (reads AND writes) before CTA exit: unambiguous under
        // graph replay, and the drain of this CTA overlaps the fill phase
        // of the ~6 other CTAs resident on the SM.
        asm volatile("cp.async.bulk.wait_group 0;" ::: "memory");
    }
}

extern "C" void kernel_launch(void* const* d_in, const int* in_sizes, int n_in,
                              void* d_out, int out_size)
{
    const float* emb = (const float*)d_in[0];   // [2048, 32] f32
    const float* w   = (const float*)d_in[1];   // [2048]     f32
    float* out       = (float*)d_out;

    no_sparsity_tma_kernel<<<N_CHUNKS, 256>>>(emb, w, out);
}